// round 2
// baseline (speedup 1.0000x reference)
#include <cuda_runtime.h>
#include <math.h>
#include <stdint.h>

#define NN 8192
#define DD 128

static __device__ float g_E[NN * DD];
static __device__ float g_invnorm[NN];
static __device__ float g_Q[NN * DD];
static __device__ float g_K[NN * DD];
static __device__ float g_V[NN * DD];
static __device__ float g_SIM[(size_t)NN * NN];   // sim matrix
static __device__ float g_P[(size_t)NN * NN];     // attn scores, then probs (in-place)
static __device__ unsigned char g_code[(size_t)NN * NN];
static __device__ float g_invp[NN];
static __device__ float g_invn[NN];
static __device__ float g_any[NN];
static __device__ float g_pos[NN * DD];
static __device__ float g_neg[NN * DD];
static __device__ float g_bnd[NN * DD];
static __device__ float g_agg[NN * DD];

// ---------------- init: g_E = concept_embed ----------------
__global__ void init_kernel(const float* __restrict__ emb) {
    int idx = blockIdx.x * 256 + threadIdx.x;
    g_E[idx] = emb[idx];
}

// ---------------- row norms (one warp per row) ----------------
__global__ void norm_kernel() {
    int gw = (blockIdx.x * blockDim.x + threadIdx.x) >> 5;
    if (gw >= NN) return;
    int lane = threadIdx.x & 31;
    float4 v = *(const float4*)(g_E + (size_t)gw * DD + lane * 4);
    float s = v.x * v.x + v.y * v.y + v.z * v.z + v.w * v.w;
    #pragma unroll
    for (int o = 16; o > 0; o >>= 1) s += __shfl_xor_sync(0xFFFFFFFFu, s, o);
    if (lane == 0) g_invnorm[gw] = 1.0f / fmaxf(sqrtf(s), 1e-8f);
}

// ---------------- QKV projections (8 rows per block) ----------------
__global__ __launch_bounds__(128) void qkv_kernel(
    const float* __restrict__ wq, const float* __restrict__ bq,
    const float* __restrict__ wk, const float* __restrict__ bk,
    const float* __restrict__ wv, const float* __restrict__ bv)
{
    __shared__ float e[8][DD];
    int i0 = blockIdx.x * 8;
    int t = threadIdx.x;
    #pragma unroll
    for (int r = 0; r < 8; r++) e[r][t] = g_E[(size_t)(i0 + r) * DD + t];
    __syncthreads();
    float q[8], k[8], v[8];
    float bqv = bq[t], bkv = bk[t], bvv = bv[t];
    #pragma unroll
    for (int r = 0; r < 8; r++) { q[r] = bqv; k[r] = bkv; v[r] = bvv; }
    #pragma unroll 4
    for (int kk = 0; kk < DD; kk++) {
        float a = wq[kk * DD + t];
        float b = wk[kk * DD + t];
        float c = wv[kk * DD + t];
        #pragma unroll
        for (int r = 0; r < 8; r++) {
            float x = e[r][kk];
            q[r] += x * a; k[r] += x * b; v[r] += x * c;
        }
    }
    #pragma unroll
    for (int r = 0; r < 8; r++) {
        size_t o = (size_t)(i0 + r) * DD + t;
        g_Q[o] = q[r]; g_K[o] = k[r]; g_V[o] = v[r];
    }
}

// ---------------- big GEMM: C[N,N] = A[N,128] * B[N,128]^T (scaled) ----------------
// mode 0: A=B=g_E, C=g_SIM, C *= invnorm[i]*invnorm[j]   (cosine sim)
// mode 1: A=g_Q, B=g_K, C=g_P, C *= 1/sqrt(D)            (attention scores)
// NOTE: globals are bound INSIDE device code — __device__ symbols must never
// be passed as kernel arguments from host (host shadow address + GB300 ATS
// silently reads/writes host memory).
__global__ __launch_bounds__(256, 1) void gemm_nt_kernel(int mode)
{
    extern __shared__ float sm[];
    float* As = sm;                 // [128][129]
    float* Bs = sm + 128 * 129;     // [128][129]
    const float* A = (mode == 0) ? g_E : g_Q;
    const float* B = (mode == 0) ? g_E : g_K;
    float* C       = (mode == 0) ? g_SIM : g_P;
    const float inv_sqrt_d = 0.08838834764831845f;  // 1/sqrt(128)

    int tid = threadIdx.x;
    int m0 = blockIdx.y * 128;
    int n0 = blockIdx.x * 128;

    int lr = tid >> 5;              // 0..7
    int c4 = (tid & 31) * 4;        // 0..124
    #pragma unroll
    for (int p = 0; p < 16; p++) {
        int row = p * 8 + lr;
        float4 va = *(const float4*)(A + (size_t)(m0 + row) * DD + c4);
        As[row * 129 + c4 + 0] = va.x; As[row * 129 + c4 + 1] = va.y;
        As[row * 129 + c4 + 2] = va.z; As[row * 129 + c4 + 3] = va.w;
        float4 vb = *(const float4*)(B + (size_t)(n0 + row) * DD + c4);
        Bs[row * 129 + c4 + 0] = vb.x; Bs[row * 129 + c4 + 1] = vb.y;
        Bs[row * 129 + c4 + 2] = vb.z; Bs[row * 129 + c4 + 3] = vb.w;
    }
    __syncthreads();

    int tx = tid & 15, ty = tid >> 4;
    float acc[8][8];
    #pragma unroll
    for (int i = 0; i < 8; i++)
        #pragma unroll
        for (int j = 0; j < 8; j++) acc[i][j] = 0.0f;

    #pragma unroll 4
    for (int k = 0; k < 128; k++) {
        float a[8], b[8];
        #pragma unroll
        for (int i = 0; i < 8; i++) a[i] = As[(ty + 16 * i) * 129 + k];
        #pragma unroll
        for (int j = 0; j < 8; j++) b[j] = Bs[(tx + 16 * j) * 129 + k];
        #pragma unroll
        for (int i = 0; i < 8; i++)
            #pragma unroll
            for (int j = 0; j < 8; j++) acc[i][j] += a[i] * b[j];
    }

    float sa[8], sb[8];
    #pragma unroll
    for (int i = 0; i < 8; i++)
        sa[i] = (mode == 0) ? g_invnorm[m0 + ty + 16 * i] : inv_sqrt_d;
    #pragma unroll
    for (int j = 0; j < 8; j++)
        sb[j] = (mode == 0) ? g_invnorm[n0 + tx + 16 * j] : 1.0f;

    #pragma unroll
    for (int i = 0; i < 8; i++) {
        size_t m = (size_t)(m0 + ty + 16 * i);
        #pragma unroll
        for (int j = 0; j < 8; j++) {
            int n = n0 + tx + 16 * j;
            C[m * NN + n] = acc[i][j] * sa[i] * sb[j];
        }
    }
}

// ---------------- per-row classify + masked softmax ----------------
__device__ __forceinline__ float block_sum256(float v, float* buf) {
    int t = threadIdx.x;
    buf[t] = v; __syncthreads();
    #pragma unroll
    for (int s = 128; s > 0; s >>= 1) {
        if (t < s) buf[t] += buf[t + s];
        __syncthreads();
    }
    float r = buf[0]; __syncthreads();
    return r;
}
__device__ __forceinline__ float block_max256(float v, float* buf) {
    int t = threadIdx.x;
    buf[t] = v; __syncthreads();
    #pragma unroll
    for (int s = 128; s > 0; s >>= 1) {
        if (t < s) buf[t] = fmaxf(buf[t], buf[t + s]);
        __syncthreads();
    }
    float r = buf[0]; __syncthreads();
    return r;
}

__global__ __launch_bounds__(256) void classify_kernel(const float* __restrict__ adj) {
    __shared__ float s2s[NN];            // 32 KB
    __shared__ unsigned char cds[NN];    // 8 KB
    __shared__ float rbuf[256];
    const float ALPHA = 0.7f, BETA = 0.3f, LAM = 0.1f;
    int i = blockIdx.x, tid = threadIdx.x;
    size_t base = (size_t)i * NN;

    float cp = 0.f, cn = 0.f, ca = 0.f, mx = -INFINITY;
    for (int j = tid; j < NN; j += 256) {
        float a = adj[base + j];
        float sim = g_SIM[base + j];
        float s2 = g_P[base + j];
        int c = 0;
        if (a != 0.0f) {
            ca += 1.0f;
            c = (sim >= ALPHA) ? 1 : ((sim <= BETA) ? 2 : 3);
        }
        cds[j] = (unsigned char)c;
        s2s[j] = s2;
        cp += (c == 1) ? 1.0f : 0.0f;
        cn += (c == 2) ? 1.0f : 0.0f;
        if (c == 3) mx = fmaxf(mx, s2);
    }
    cp = block_sum256(cp, rbuf);
    cn = block_sum256(cn, rbuf);
    ca = block_sum256(ca, rbuf);
    mx = block_max256(mx, rbuf);
    if (mx == -INFINITY) mx = 0.0f;   // safe max when boundary region empty

    float s = 0.f;
    for (int j = tid; j < NN; j += 256) {
        float e = (cds[j] == 3) ? expf(s2s[j] - mx) : 0.0f;
        s2s[j] = e;
        s += e;
    }
    s = block_sum256(s, rbuf);
    float inv = 1.0f / fmaxf(s, 1e-30f);

    for (int j = tid; j < NN; j += 256) {
        g_P[base + j] = s2s[j] * inv;
        g_code[base + j] = cds[j];
    }
    if (tid == 0) {
        g_invp[i] = 1.0f / fmaxf(cp, 1.0f);
        g_invn[i] = LAM / fmaxf(cn, 1.0f);
        g_any[i] = (ca > 0.0f) ? 1.0f : 0.0f;
    }
}

// ---------------- region accumulation: pos/neg/bnd embeddings ----------------
// block: 64 i-rows x 64 d-cols; loop all j in 64-tiles; 3 accumulators share loads
__global__ __launch_bounds__(256) void region_kernel() {
    extern __shared__ float sm[];
    float* Ps = sm;                           // [64][65]
    float* Es = sm + 64 * 65;                 // [64][65]
    float* Vs = sm + 2 * 64 * 65;             // [64][65]
    unsigned char* Cs = (unsigned char*)(sm + 3 * 64 * 65); // [64][64]

    int tid = threadIdx.x;
    int i0 = blockIdx.x * 64;
    int dh = blockIdx.y * 64;
    int di = tid & 15;    // d fragment index
    int ii = tid >> 4;    // i fragment index (0..15)

    float ap[4][4], an[4][4], ab[4][4];
    #pragma unroll
    for (int a = 0; a < 4; a++)
        #pragma unroll
        for (int b = 0; b < 4; b++) { ap[a][b] = 0.f; an[a][b] = 0.f; ab[a][b] = 0.f; }

    int lr = tid >> 4;            // 0..15 (load row group)
    int c4 = (tid & 15) * 4;      // 0..60

    for (int j0 = 0; j0 < NN; j0 += 64) {
        __syncthreads();
        // code tile: 4096 bytes, one uint4 per thread
        {
            int row = tid >> 2, cc = (tid & 3) * 16;
            *(uint4*)(Cs + row * 64 + cc) =
                *(const uint4*)(g_code + (size_t)(i0 + row) * NN + j0 + cc);
        }
        #pragma unroll
        for (int p = 0; p < 4; p++) {
            int row = p * 16 + lr;
            float4 vp = *(const float4*)(g_P + (size_t)(i0 + row) * NN + j0 + c4);
            Ps[row * 65 + c4 + 0] = vp.x; Ps[row * 65 + c4 + 1] = vp.y;
            Ps[row * 65 + c4 + 2] = vp.z; Ps[row * 65 + c4 + 3] = vp.w;
            float4 ve = *(const float4*)(g_E + (size_t)(j0 + row) * DD + dh + c4);
            Es[row * 65 + c4 + 0] = ve.x; Es[row * 65 + c4 + 1] = ve.y;
            Es[row * 65 + c4 + 2] = ve.z; Es[row * 65 + c4 + 3] = ve.w;
            float4 vv = *(const float4*)(g_V + (size_t)(j0 + row) * DD + dh + c4);
            Vs[row * 65 + c4 + 0] = vv.x; Vs[row * 65 + c4 + 1] = vv.y;
            Vs[row * 65 + c4 + 2] = vv.z; Vs[row * 65 + c4 + 3] = vv.w;
        }
        __syncthreads();

        #pragma unroll 4
        for (int jj = 0; jj < 64; jj++) {
            float be[4], bv[4];
            #pragma unroll
            for (int r = 0; r < 4; r++) {
                be[r] = Es[jj * 65 + di + 16 * r];
                bv[r] = Vs[jj * 65 + di + 16 * r];
            }
            #pragma unroll
            for (int ic = 0; ic < 4; ic++) {
                int irow = ii + 16 * ic;
                int c = Cs[irow * 64 + jj];
                float p = Ps[irow * 65 + jj];
                float fp = (c == 1) ? 1.0f : 0.0f;
                float fn = (c == 2) ? 1.0f : 0.0f;
                #pragma unroll
                for (int r = 0; r < 4; r++) {
                    ap[ic][r] += fp * be[r];
                    an[ic][r] += fn * be[r];
                    ab[ic][r] += p  * bv[r];
                }
            }
        }
    }

    #pragma unroll
    for (int ic = 0; ic < 4; ic++) {
        int ig = i0 + ii + 16 * ic;
        float vp = g_invp[ig], vn = g_invn[ig];
        #pragma unroll
        for (int r = 0; r < 4; r++) {
            int d = dh + di + 16 * r;
            size_t o = (size_t)ig * DD + d;
            g_pos[o] = ap[ic][r] * vp;
            g_neg[o] = an[ic][r] * vn;
            g_bnd[o] = ab[ic][r];
        }
    }
}

// ---------------- gating MLP + fusion (8 rows per block) ----------------
__global__ __launch_bounds__(256) void gate_kernel(
    const float* __restrict__ g1w, const float* __restrict__ g1b,
    const float* __restrict__ g2w, const float* __restrict__ g2b)
{
    __shared__ float x[8][512];     // concat [E,pos,bnd,neg]
    __shared__ float h[8][257];
    __shared__ float gates[8][4];
    int i0 = blockIdx.x * 8;
    int t = threadIdx.x;

    for (int q = t; q < 8 * 128; q += 256) {
        int r = q >> 7, d = q & 127;
        size_t o = (size_t)(i0 + r) * DD + d;
        x[r][d]       = g_E[o];
        x[r][128 + d] = g_pos[o];
        x[r][256 + d] = g_bnd[o];
        x[r][384 + d] = g_neg[o];
    }
    __syncthreads();

    float acc[8];
    float bb = g1b[t];
    #pragma unroll
    for (int r = 0; r < 8; r++) acc[r] = bb;
    #pragma unroll 4
    for (int kk = 0; kk < 512; kk++) {
        float w = g1w[kk * 256 + t];
        #pragma unroll
        for (int r = 0; r < 8; r++) acc[r] += x[r][kk] * w;
    }
    #pragma unroll
    for (int r = 0; r < 8; r++) h[r][t] = fmaxf(acc[r], 0.0f);
    __syncthreads();

    int wid = t >> 5, lane = t & 31;
    {
        int r = wid;   // 8 warps, one row each
        float l0 = 0, l1 = 0, l2 = 0, l3 = 0;
        for (int kk = lane; kk < 256; kk += 32) {
            float hv = h[r][kk];
            l0 += hv * g2w[kk * 4 + 0];
            l1 += hv * g2w[kk * 4 + 1];
            l2 += hv * g2w[kk * 4 + 2];
            l3 += hv * g2w[kk * 4 + 3];
        }
        #pragma unroll
        for (int o = 16; o > 0; o >>= 1) {
            l0 += __shfl_xor_sync(0xFFFFFFFFu, l0, o);
            l1 += __shfl_xor_sync(0xFFFFFFFFu, l1, o);
            l2 += __shfl_xor_sync(0xFFFFFFFFu, l2, o);
            l3 += __shfl_xor_sync(0xFFFFFFFFu, l3, o);
        }
        if (lane == 0) {
            l0 += g2b[0]; l1 += g2b[1]; l2 += g2b[2]; l3 += g2b[3];
            float m = fmaxf(fmaxf(l0, l1), fmaxf(l2, l3));
            float e0 = expf(l0 - m), e1 = expf(l1 - m), e2 = expf(l2 - m), e3 = expf(l3 - m);
            float inv = 1.0f / (e0 + e1 + e2 + e3);
            gates[r][0] = e0 * inv; gates[r][1] = e1 * inv;
            gates[r][2] = e2 * inv; gates[r][3] = e3 * inv;
        }
    }
    __syncthreads();

    for (int q = t; q < 8 * 128; q += 256) {
        int r = q >> 7, d = q & 127;
        float any = g_any[i0 + r];
        float f;
        if (any != 0.0f)
            f = gates[r][0] * x[r][d] + gates[r][1] * x[r][128 + d]
              + gates[r][2] * x[r][256 + d] + gates[r][3] * x[r][384 + d];
        else
            f = x[r][d];
        g_agg[(size_t)(i0 + r) * DD + d] = f;
    }
}

// ---------------- graph-conv layer + output accumulation ----------------
__global__ __launch_bounds__(128) void gc_kernel(
    const float* __restrict__ gcw, const float* __restrict__ gcb,
    const float* __restrict__ lwp, int l, float* __restrict__ out)
{
    __shared__ float a[8][DD];
    int i0 = blockIdx.x * 8;
    int t = threadIdx.x;
    #pragma unroll
    for (int r = 0; r < 8; r++) a[r][t] = g_agg[(size_t)(i0 + r) * DD + t];
    __syncthreads();

    float acc[8];
    float b = gcb[t];
    #pragma unroll
    for (int r = 0; r < 8; r++) acc[r] = b;
    #pragma unroll 4
    for (int kk = 0; kk < DD; kk++) {
        float w = gcw[kk * DD + t];
        #pragma unroll
        for (int r = 0; r < 8; r++) acc[r] += a[r][kk] * w;
    }

    float w0 = lwp[0], w1 = lwp[1];
    float m = fmaxf(w0, w1);
    float e0 = expf(w0 - m), e1 = expf(w1 - m);
    float lw = ((l == 0) ? e0 : e1) / (e0 + e1);

    #pragma unroll
    for (int r = 0; r < 8; r++) {
        float v = fmaxf(acc[r], 0.0f);
        size_t o = (size_t)(i0 + r) * DD + t;
        g_E[o] = v;  // input to next layer
        if (l == 0) out[o] = lw * v;
        else        out[o] += lw * v;
    }
}

// ---------------- host launcher ----------------
extern "C" void kernel_launch(void* const* d_in, const int* in_sizes, int n_in,
                              void* d_out, int out_size)
{
    const float* adj  = (const float*)d_in[0];
    const float* emb  = (const float*)d_in[1];
    const float* gc_w = (const float*)d_in[2];
    const float* gc_b = (const float*)d_in[3];
    const float* wq   = (const float*)d_in[4];
    const float* bq   = (const float*)d_in[5];
    const float* wk   = (const float*)d_in[6];
    const float* bk   = (const float*)d_in[7];
    const float* wv   = (const float*)d_in[8];
    const float* bv   = (const float*)d_in[9];
    const float* g1w  = (const float*)d_in[10];
    const float* g1b  = (const float*)d_in[11];
    const float* g2w  = (const float*)d_in[12];
    const float* g2b  = (const float*)d_in[13];
    const float* lw   = (const float*)d_in[14];
    float* out = (float*)d_out;

    const int gemm_smem = 2 * 128 * 129 * 4;                   // 132096
    const int region_smem = 3 * 64 * 65 * 4 + 64 * 64;          // 54016
    cudaFuncSetAttribute(gemm_nt_kernel, cudaFuncAttributeMaxDynamicSharedMemorySize, gemm_smem);
    cudaFuncSetAttribute(region_kernel, cudaFuncAttributeMaxDynamicSharedMemorySize, region_smem);

    init_kernel<<<(NN * DD) / 256, 256>>>(emb);

    for (int l = 0; l < 2; l++) {
        norm_kernel<<<NN * 32 / 256, 256>>>();
        qkv_kernel<<<NN / 8, 128>>>(wq, bq, wk, bk, wv, bv);
        // sim = (E E^T) * invn_i * invn_j
        gemm_nt_kernel<<<dim3(64, 64), 256, gemm_smem>>>(0);
        // s = (Q K^T) / sqrt(D)
        gemm_nt_kernel<<<dim3(64, 64), 256, gemm_smem>>>(1);
        classify_kernel<<<NN, 256>>>(adj);
        region_kernel<<<dim3(NN / 64, 2), 256, region_smem>>>();
        gate_kernel<<<NN / 8, 256>>>(g1w, g1b, g2w, g2b);
        gc_kernel<<<NN / 8, 128>>>(gc_w + (size_t)l * DD * DD, gc_b + (size_t)l * DD,
                                   lw, l, out);
    }
}